// round 17
// baseline (speedup 1.0000x reference)
#include <cuda_runtime.h>
#include <cuda_bf16.h>
#include <cstdint>
#include <cstddef>

// Problem constants
#define BATCH 8
#define SLEN 1024
#define DMODEL 1024
#define NHEADS 16
#define DK 64
#define MROWS (BATCH * SLEN)   // 8192

// ---------------- scratch (device globals; no allocation allowed) ------------
__device__ float g_Q[MROWS * DMODEL];
__device__ float g_K[MROWS * DMODEL];
__device__ float g_V[MROWS * DMODEL];
__device__ float g_X[MROWS * DMODEL];
// tf32-pre-rounded copies
__device__ float g_Rq[MROWS * DMODEL];
__device__ float g_Rk[MROWS * DMODEL];
__device__ float g_Rv[MROWS * DMODEL];
__device__ float g_Rw[4 * DMODEL * DMODEL];   // wq, wk, wv, dense

// =================== PTX helpers =============================================
static __device__ __forceinline__ uint32_t smem_u32(const void* p) {
    uint32_t a;
    asm("{ .reg .u64 t; cvta.to.shared.u64 t, %1; cvt.u32.u64 %0, t; }"
        : "=r"(a) : "l"(p));
    return a;
}

#define CP_ASYNC16(dst, src) \
    asm volatile("cp.async.cg.shared.global [%0], [%1], 16;" \
                 :: "r"(dst), "l"(src) : "memory")
#define CP_COMMIT() asm volatile("cp.async.commit_group;" ::: "memory")
#define CP_WAIT1()  asm volatile("cp.async.wait_group 1;" ::: "memory")

static __device__ __forceinline__ uint32_t f2tf32(float x) {
    uint32_t r;
    asm("cvt.rna.tf32.f32 %0, %1;" : "=r"(r) : "f"(x));
    return r;
}
static __device__ __forceinline__ float rnd_tf32(float x) {
    return __uint_as_float(f2tf32(x));
}

#define LDSM_X4(r0, r1, r2, r3, addr) \
    asm volatile("ldmatrix.sync.aligned.m8n8.x4.shared.b16 {%0,%1,%2,%3}, [%4];" \
                 : "=r"(r0), "=r"(r1), "=r"(r2), "=r"(r3) : "r"(addr))

#define MMA_TF32(c, a, b) \
    asm volatile("mma.sync.aligned.m16n8k8.row.col.f32.tf32.tf32.f32 " \
                 "{%0,%1,%2,%3}, {%4,%5,%6,%7}, {%8,%9}, {%0,%1,%2,%3};" \
                 : "+f"((c)[0]), "+f"((c)[1]), "+f"((c)[2]), "+f"((c)[3]) \
                 : "r"((a)[0]), "r"((a)[1]), "r"((a)[2]), "r"((a)[3]), \
                   "r"((b)[0]), "r"((b)[1]))

#define MMA_TF32_4(c, a0, a1, a2, a3, b0, b1) \
    asm volatile("mma.sync.aligned.m16n8k8.row.col.f32.tf32.tf32.f32 " \
                 "{%0,%1,%2,%3}, {%4,%5,%6,%7}, {%8,%9}, {%0,%1,%2,%3};" \
                 : "+f"((c)[0]), "+f"((c)[1]), "+f"((c)[2]), "+f"((c)[3]) \
                 : "r"(a0), "r"(a1), "r"(a2), "r"(a3), "r"(b0), "r"(b1))

// =================== tf32 pre-round passes ===================================
__global__ __launch_bounds__(256) void round_inputs(
    const float* __restrict__ q, const float* __restrict__ k,
    const float* __restrict__ v,
    float* __restrict__ rq, float* __restrict__ rk, float* __restrict__ rv)
{
    const float* s; float* d;
    if (blockIdx.z == 0)      { s = q; d = rq; }
    else if (blockIdx.z == 1) { s = k; d = rk; }
    else                      { s = v; d = rv; }
    size_t i = ((size_t)blockIdx.x * 256 + threadIdx.x) * 4;
    float4 x = *(const float4*)&s[i];
    x.x = rnd_tf32(x.x); x.y = rnd_tf32(x.y);
    x.z = rnd_tf32(x.z); x.w = rnd_tf32(x.w);
    *(float4*)&d[i] = x;
}

__global__ __launch_bounds__(256) void round_weights(
    const float* __restrict__ w0, const float* __restrict__ w1,
    const float* __restrict__ w2, const float* __restrict__ w3,
    float* __restrict__ dst)
{
    const float* s;
    if (blockIdx.z == 0)      s = w0;
    else if (blockIdx.z == 1) s = w1;
    else if (blockIdx.z == 2) s = w2;
    else                      s = w3;
    size_t i = ((size_t)blockIdx.x * 256 + threadIdx.x) * 4;
    float4 x = *(const float4*)&s[i];
    x.x = rnd_tf32(x.x); x.y = rnd_tf32(x.y);
    x.z = rnd_tf32(x.z); x.w = rnd_tf32(x.w);
    *(float4*)&dst[(size_t)blockIdx.z * DMODEL * DMODEL + i] = x;
}

// =================== tf32 mma.sync NT GEMM body ==============================
// C[M,N] = A[M,K] @ W[N,K]^T + bias.  CTA 128x128, BK=32, 3-stage cp.async.
// A and B fragments both via ldmatrix (b16-reinterpret trick).
#define GSTAGES 3
#define ASTRIDE 36
#define ATILE_WORDS (128 * ASTRIDE)
#define STAGE_BYTES (2 * ATILE_WORDS * 4)
#define GEMM_SMEM (GSTAGES * STAGE_BYTES)   // 110592

template <bool ROUND_OUT>
static __device__ __forceinline__ void gemm_body(
    float* dynf,
    const float* __restrict__ A, const float* __restrict__ W,
    const float* __restrict__ bias, float* __restrict__ C,
    int M, int N, int K, int bm, int bn)
{
    const uint32_t smbase = smem_u32(dynf);
    const int tid = threadIdx.x;
    const int wid = tid >> 5;
    const int lane = tid & 31;
    const int g = lane >> 2;
    const int t = lane & 3;
    const int warp_m = wid >> 2;
    const int warp_n = wid & 3;
    const int mbase = warp_m * 64;
    const int nbase = warp_n * 32;
    const int lrow = ((lane >> 3) & 1) * 8 + (lane & 7);
    const int lcolb = (lane >> 4) * 16;
    const int brow = lane & 7;
    const int bmatb = (lane >> 3) * 16;

    const int nchunks = K / 32;

    const float* Abase = A + (size_t)bm * K;
    const float* Bbase = W + (size_t)bn * K;

    auto load_chunk = [&](int c, int s) {
        uint32_t sa = smbase + s * STAGE_BYTES;
        uint32_t sb = sa + ATILE_WORDS * 4;
        const float* Ap = Abase + c * 32;
        const float* Bp = Bbase + c * 32;
#pragma unroll
        for (int v = 0; v < 4; v++) {
            int idx = tid + 256 * v;
            int row = idx >> 3;
            int seg = idx & 7;
            uint32_t off = (uint32_t)(row * ASTRIDE + seg * 4) * 4;
            CP_ASYNC16(sa + off, Ap + (size_t)row * K + seg * 4);
            CP_ASYNC16(sb + off, Bp + (size_t)row * K + seg * 4);
        }
    };

    float c[4][4][4];
#pragma unroll
    for (int mt = 0; mt < 4; mt++)
#pragma unroll
        for (int nt = 0; nt < 4; nt++)
#pragma unroll
            for (int r = 0; r < 4; r++) c[mt][nt][r] = 0.f;

    load_chunk(0, 0); CP_COMMIT();
    load_chunk(1, 1); CP_COMMIT();

    int s = 0;
    int sl = 2;
    for (int i = 0; i < nchunks; i++) {
        CP_WAIT1();
        __syncthreads();

        const int nxt = i + 2;
        if (nxt < nchunks) load_chunk(nxt, sl);
        CP_COMMIT();

        const uint32_t sa = smbase + s * STAGE_BYTES;
        const uint32_t sb = sa + ATILE_WORDS * 4;

#pragma unroll
        for (int ks2 = 0; ks2 < 2; ks2++) {
            uint32_t bf[4][4];
#pragma unroll
            for (int nt = 0; nt < 4; nt++) {
                uint32_t baddr = sb +
                    (uint32_t)((nbase + nt * 8 + brow) * ASTRIDE) * 4 +
                    ks2 * 64 + bmatb;
                LDSM_X4(bf[nt][0], bf[nt][1], bf[nt][2], bf[nt][3], baddr);
            }
#pragma unroll
            for (int kk = 0; kk < 2; kk++) {
                const int ks = ks2 * 2 + kk;
                uint32_t a[4][4];
#pragma unroll
                for (int mt = 0; mt < 4; mt++) {
                    uint32_t addr = sa +
                        (uint32_t)((mbase + mt * 16 + lrow) * ASTRIDE + ks * 8) * 4 + lcolb;
                    LDSM_X4(a[mt][0], a[mt][1], a[mt][2], a[mt][3], addr);
                }
#pragma unroll
                for (int mt = 0; mt < 4; mt++)
#pragma unroll
                    for (int nt = 0; nt < 4; nt++)
                        MMA_TF32_4(c[mt][nt], a[mt][0], a[mt][1], a[mt][2], a[mt][3],
                                   bf[nt][kk * 2], bf[nt][kk * 2 + 1]);
            }
        }

        s = (s == GSTAGES - 1) ? 0 : s + 1;
        sl = (sl == GSTAGES - 1) ? 0 : sl + 1;
    }

#pragma unroll
    for (int mt = 0; mt < 4; mt++) {
        const int r0 = bm + mbase + mt * 16 + g;
#pragma unroll
        for (int nt = 0; nt < 4; nt++) {
            const int col = bn + nbase + nt * 8 + 2 * t;
            const float b0 = bias[col], b1 = bias[col + 1];
            float2 o0 = make_float2(c[mt][nt][0] + b0, c[mt][nt][1] + b1);
            float2 o1 = make_float2(c[mt][nt][2] + b0, c[mt][nt][3] + b1);
            if (ROUND_OUT) {
                o0.x = rnd_tf32(o0.x); o0.y = rnd_tf32(o0.y);
                o1.x = rnd_tf32(o1.x); o1.y = rnd_tf32(o1.y);
            }
            *(float2*)&C[(size_t)r0 * N + col] = o0;
            *(float2*)&C[(size_t)(r0 + 8) * N + col] = o1;
        }
    }
}

__global__ __launch_bounds__(256, 2) void gemm_mma(
    const float* __restrict__ A, const float* __restrict__ W,
    const float* __restrict__ bias, float* __restrict__ C,
    int M, int N, int K)
{
    extern __shared__ float dynf[];
    gemm_body<false>(dynf, A, W, bias, C, M, N, K,
                     blockIdx.y * 128, blockIdx.x * 128);
}

__global__ __launch_bounds__(256, 2) void qkv_mma(
    const float* __restrict__ Aq, const float* __restrict__ Ak, const float* __restrict__ Av,
    const float* __restrict__ Wall,
    const float* __restrict__ bq, const float* __restrict__ bk, const float* __restrict__ bv,
    float* __restrict__ Cq, float* __restrict__ Ck, float* __restrict__ Cv)
{
    extern __shared__ float dynf[];
    const float* A; const float* bias; float* C;
    if (blockIdx.z == 0)      { A = Aq; bias = bq; C = Cq; }
    else if (blockIdx.z == 1) { A = Ak; bias = bk; C = Ck; }
    else                      { A = Av; bias = bv; C = Cv; }
    const float* W = Wall + (size_t)blockIdx.z * DMODEL * DMODEL;
    gemm_body<true>(dynf, A, W, bias, C, MROWS, DMODEL, DMODEL,
                    blockIdx.y * 128, blockIdx.x * 128);
}

// =================== tensor-core attention ===================================
#define AQT 128
#define AKT 64
#define QSTR 76
#define KSTR 68
#define VSTR 68
#define QWORDS (AQT * QSTR)            // 9728
#define KVWORDS (AKT * KSTR)           // 4352
#define STAGEW (2 * KVWORDS)           // 8704
#define ATTN_SMEM ((QWORDS + 2 * STAGEW + SLEN) * 4)  // 112640 B

__global__ __launch_bounds__(256, 2) void attn_tc(
    const float* __restrict__ Q, const float* __restrict__ K,
    const float* __restrict__ V, const float* __restrict__ pol,
    float* __restrict__ X)
{
    extern __shared__ float sf[];
    const uint32_t smbase = smem_u32(sf);

    const int qt = blockIdx.x;
    const int h  = blockIdx.y;
    const int b  = blockIdx.z;
    const int tid = threadIdx.x;
    const int wid = tid >> 5;
    const int lane = tid & 31;
    const int g = lane >> 2;
    const int t = lane & 3;
    const int lrow = ((lane >> 3) & 1) * 8 + (lane & 7);
    const int lcolb = (lane >> 4) * 16;
    const int brow = lane & 7;
    const int bmatb = (lane >> 3) * 16;

    const float* Qg = Q + ((size_t)(b * SLEN + qt * AQT)) * DMODEL + h * DK;
    const float* Kg = K + ((size_t)b * SLEN) * DMODEL + h * DK;
    const float* Vg = V + ((size_t)b * SLEN) * DMODEL + h * DK;
    const float* pg = pol + (size_t)b * SLEN;

    {
#pragma unroll
        for (int v = 0; v < 8; v++) {
            int idx = tid + 256 * v;
            int row = idx >> 4;
            int seg = idx & 15;
            CP_ASYNC16(smbase + (uint32_t)(row * QSTR + seg * 4) * 4,
                       Qg + (size_t)row * DMODEL + seg * 4);
        }
        CP_ASYNC16(smbase + (uint32_t)(QWORDS + 2 * STAGEW + tid * 4) * 4,
                   pg + tid * 4);
    }
    auto load_kv = [&](int kt, int s) {
        uint32_t kb = smbase + (uint32_t)(QWORDS + s * STAGEW) * 4;
        uint32_t vb = kb + KVWORDS * 4;
        const float* Kp = Kg + (size_t)(kt * AKT) * DMODEL;
        const float* Vp = Vg + (size_t)(kt * AKT) * DMODEL;
#pragma unroll
        for (int v = 0; v < 4; v++) {
            int idx = tid + 256 * v;
            int row = idx >> 4;
            int seg = idx & 15;
            uint32_t off = (uint32_t)(row * KSTR + seg * 4) * 4;
            CP_ASYNC16(kb + off, Kp + (size_t)row * DMODEL + seg * 4);
            CP_ASYNC16(vb + off, Vp + (size_t)row * DMODEL + seg * 4);
        }
    };
    load_kv(0, 0); CP_COMMIT();
    load_kv(1, 1); CP_COMMIT();

    uint32_t aq[8][4];
    float O[8][4];
    float rs0 = 0.f, rs1 = 0.f;
#pragma unroll
    for (int n2 = 0; n2 < 8; n2++)
#pragma unroll
        for (int r = 0; r < 4; r++) O[n2][r] = 0.f;

    const int ntiles = SLEN / AKT;  // 16
    for (int kt = 0; kt < ntiles; kt++) {
        const int s = kt & 1;
        CP_WAIT1();
        __syncthreads();

        if (kt == 0) {
#pragma unroll
            for (int ks = 0; ks < 8; ks++) {
                uint32_t addr = smbase +
                    (uint32_t)((wid * 16 + lrow) * QSTR + ks * 8) * 4 + lcolb;
                LDSM_X4(aq[ks][0], aq[ks][1], aq[ks][2], aq[ks][3], addr);
            }
        }

        const uint32_t kbu = smbase + (uint32_t)(QWORDS + s * STAGEW) * 4;
        const float* Vsf = sf + QWORDS + s * STAGEW + KVWORDS;

        // ---- phase 1: S = Q K^T, K via ldmatrix; ks2-outer so the 8 sc[nt]
        //      accumulators form independent chains (no back-to-back RAW) ----
        float sc[8][4];
#pragma unroll
        for (int nt = 0; nt < 8; nt++)
#pragma unroll
            for (int r = 0; r < 4; r++) sc[nt][r] = 0.f;

#pragma unroll
        for (int ks2 = 0; ks2 < 4; ks2++) {
#pragma unroll
            for (int nt = 0; nt < 8; nt++) {
                uint32_t r0, r1, r2, r3;
                uint32_t baddr = kbu +
                    (uint32_t)((nt * 8 + brow) * KSTR) * 4 + ks2 * 64 + bmatb;
                LDSM_X4(r0, r1, r2, r3, baddr);
                MMA_TF32_4(sc[nt], aq[2 * ks2][0], aq[2 * ks2][1],
                           aq[2 * ks2][2], aq[2 * ks2][3], r0, r1);
                MMA_TF32_4(sc[nt], aq[2 * ks2 + 1][0], aq[2 * ks2 + 1][1],
                           aq[2 * ks2 + 1][2], aq[2 * ks2 + 1][3], r2, r3);
            }
        }

        const float* pk = sf + QWORDS + 2 * STAGEW + kt * AKT;
#pragma unroll
        for (int nt = 0; nt < 8; nt++) {
            float p0 = pk[nt * 8 + 2 * t];
            float p1 = pk[nt * 8 + 2 * t + 1];
            float e0 = __expf(sc[nt][0] * 0.125f) * p0;
            float e1 = __expf(sc[nt][1] * 0.125f) * p1;
            float e2 = __expf(sc[nt][2] * 0.125f) * p0;
            float e3 = __expf(sc[nt][3] * 0.125f) * p1;
            rs0 += e0 + e1;
            rs1 += e2 + e3;
            sc[nt][0] = __uint_as_float(f2tf32(e0));
            sc[nt][1] = __uint_as_float(f2tf32(e1));
            sc[nt][2] = __uint_as_float(f2tf32(e2));
            sc[nt][3] = __uint_as_float(f2tf32(e3));
        }

        // ---- phase 2: O += P V (n2-inner: 8 independent O chains) ----
#pragma unroll
        for (int k2 = 0; k2 < 8; k2++) {
            const float* vrow = Vsf + (k2 * 8 + 2 * t) * VSTR;
            uint32_t pa0 = __float_as_uint(sc[k2][0]);
            uint32_t pa1 = __float_as_uint(sc[k2][2]);
            uint32_t pa2 = __float_as_uint(sc[k2][1]);
            uint32_t pa3 = __float_as_uint(sc[k2][3]);
#pragma unroll
            for (int n2 = 0; n2 < 8; n2++) {
                uint32_t b0 = __float_as_uint(vrow[n2 * 8 + g]);
                uint32_t b1 = __float_as_uint(vrow[VSTR + n2 * 8 + g]);
                MMA_TF32_4(O[n2], pa0, pa1, pa2, pa3, b0, b1);
            }
        }

        __syncthreads();
        if (kt + 2 < ntiles) load_kv(kt + 2, s);
        CP_COMMIT();
    }

    rs0 += __shfl_xor_sync(0xffffffffu, rs0, 1);
    rs0 += __shfl_xor_sync(0xffffffffu, rs0, 2);
    rs1 += __shfl_xor_sync(0xffffffffu, rs1, 1);
    rs1 += __shfl_xor_sync(0xffffffffu, rs1, 2);
    const float i0 = 1.f / (rs0 + 1e-6f);
    const float i1 = 1.f / (rs1 + 1e-6f);

    float* Xg = X + ((size_t)(b * SLEN + qt * AQT + wid * 16)) * DMODEL + h * DK;
#pragma unroll
    for (int n2 = 0; n2 < 8; n2++) {
        int col = n2 * 8 + 2 * t;
        float2 o0 = make_float2(rnd_tf32(O[n2][0] * i0), rnd_tf32(O[n2][1] * i0));
        float2 o1 = make_float2(rnd_tf32(O[n2][2] * i1), rnd_tf32(O[n2][3] * i1));
        *(float2*)&Xg[(size_t)g * DMODEL + col] = o0;
        *(float2*)&Xg[(size_t)(g + 8) * DMODEL + col] = o1;
    }
}

// ---------------- launch ------------------------------------------------------
extern "C" void kernel_launch(void* const* d_in, const int* in_sizes, int n_in,
                              void* d_out, int out_size)
{
    const float* query   = (const float*)d_in[0];
    const float* key     = (const float*)d_in[1];
    const float* value   = (const float*)d_in[2];
    const float* policy  = (const float*)d_in[3];
    const float* wq_w    = (const float*)d_in[4];
    const float* wq_b    = (const float*)d_in[5];
    const float* wk_w    = (const float*)d_in[6];
    const float* wk_b    = (const float*)d_in[7];
    const float* wv_w    = (const float*)d_in[8];
    const float* wv_b    = (const float*)d_in[9];
    const float* dense_w = (const float*)d_in[10];
    const float* dense_b = (const float*)d_in[11];
    float* out = (float*)d_out;

    float *Qp, *Kp, *Vp, *Xp, *Rq, *Rk, *Rv, *Rw;
    cudaGetSymbolAddress((void**)&Qp, g_Q);
    cudaGetSymbolAddress((void**)&Kp, g_K);
    cudaGetSymbolAddress((void**)&Vp, g_V);
    cudaGetSymbolAddress((void**)&Xp, g_X);
    cudaGetSymbolAddress((void**)&Rq, g_Rq);
    cudaGetSymbolAddress((void**)&Rk, g_Rk);
    cudaGetSymbolAddress((void**)&Rv, g_Rv);
    cudaGetSymbolAddress((void**)&Rw, g_Rw);

    cudaFuncSetAttribute(gemm_mma, cudaFuncAttributeMaxDynamicSharedMemorySize, GEMM_SMEM);
    cudaFuncSetAttribute(qkv_mma,  cudaFuncAttributeMaxDynamicSharedMemorySize, GEMM_SMEM);
    cudaFuncSetAttribute(attn_tc,  cudaFuncAttributeMaxDynamicSharedMemorySize, ATTN_SMEM);

    dim3 gri(MROWS * DMODEL / 1024, 1, 3);   // (8192, 1, 3)
    round_inputs<<<gri, 256>>>(query, key, value, Rq, Rk, Rv);
    dim3 grw(DMODEL * DMODEL / 1024, 1, 4);  // (1024, 1, 4)
    round_weights<<<grw, 256>>>(wq_w, wk_w, wv_w, dense_w, Rw);

    dim3 gqkv(DMODEL / 128, MROWS / 128, 3);  // (8, 64, 3)
    qkv_mma<<<gqkv, 256, GEMM_SMEM>>>(Rq, Rk, Rv, Rw,
                                      wq_b, wk_b, wv_b,
                                      Qp, Kp, Vp);

    dim3 gattn(SLEN / AQT, NHEADS, BATCH);  // (8, 16, 8)
    attn_tc<<<gattn, 256, ATTN_SMEM>>>(Qp, Kp, Vp, policy, Xp);

    dim3 gblk(DMODEL / 128, MROWS / 128);  // (8, 64)
    gemm_mma<<<gblk, 256, GEMM_SMEM>>>(Xp, Rw + (size_t)3 * DMODEL * DMODEL,
                                       dense_b, out, MROWS, DMODEL, DMODEL);
}